// round 14
// baseline (speedup 1.0000x reference)
#include <cuda_runtime.h>
#include <cuda_bf16.h>
#include <math.h>
#include <stdint.h>

// Problem constants
#define Bb 2
#define Ss 2048
#define DM 1024
#define Hh 16
#define Dd 64
#define Nn (Bb*Ss)          // 4096 tokens
#define BH (Bb*Hh)          // 32

#define QSCALE (0.125f * 1.4426950408889634f)   // 1/sqrt(64) * log2(e)

// Scratch (device globals)
__device__ __nv_bfloat16 g_Ahi[Nn*DM], g_Alo[Nn*DM];          // activations (x, then attn-out)
__device__ __nv_bfloat16 g_Whi[4][DM*DM], g_Wlo[4][DM*DM];    // wq, wk, wv, wo
__device__ __nv_bfloat16 g_Qhi[BH*Ss*Dd], g_Qlo[BH*Ss*Dd];    // [bh][s][d], rope'd + scaled
__device__ __nv_bfloat16 g_Khi[BH*Ss*Dd], g_Klo[BH*Ss*Dd];    // [bh][s][d], rope'd
__device__ __nv_bfloat16 g_Vhi[BH*Ss*Dd], g_Vlo[BH*Ss*Dd];    // [bh][s][d]

// ===========================================================================
// PTX helpers
// ===========================================================================
__device__ __forceinline__ uint32_t smem_u32(const void* p) {
    uint32_t a;
    asm("{ .reg .u64 t; cvta.to.shared.u64 t, %1; cvt.u32.u64 %0, t; }"
        : "=r"(a) : "l"(p));
    return a;
}

#define CP_ASYNC16(dst, src) \
    asm volatile("cp.async.cg.shared.global [%0], [%1], 16;" \
                 :: "r"(dst), "l"(src) : "memory")
#define CP_COMMIT() asm volatile("cp.async.commit_group;" ::: "memory")
#define CP_WAIT(n)  asm volatile("cp.async.wait_group %0;" :: "n"(n) : "memory")

__device__ __forceinline__ void ldsm_x4(uint32_t* r, uint32_t addr) {
    asm volatile("ldmatrix.sync.aligned.m8n8.x4.shared.b16 {%0,%1,%2,%3}, [%4];"
                 : "=r"(r[0]), "=r"(r[1]), "=r"(r[2]), "=r"(r[3]) : "r"(addr));
}
__device__ __forceinline__ void ldsm_x4_t(uint32_t* r, uint32_t addr) {
    asm volatile("ldmatrix.sync.aligned.m8n8.x4.trans.shared.b16 {%0,%1,%2,%3}, [%4];"
                 : "=r"(r[0]), "=r"(r[1]), "=r"(r[2]), "=r"(r[3]) : "r"(addr));
}
__device__ __forceinline__ void mma_bf16(float* c, const uint32_t* a,
                                         const uint32_t* b) {
    asm volatile(
        "mma.sync.aligned.m16n8k16.row.col.f32.bf16.bf16.f32 "
        "{%0,%1,%2,%3}, {%4,%5,%6,%7}, {%8,%9}, {%0,%1,%2,%3};"
        : "+f"(c[0]), "+f"(c[1]), "+f"(c[2]), "+f"(c[3])
        : "r"(a[0]), "r"(a[1]), "r"(a[2]), "r"(a[3]), "r"(b[0]), "r"(b[1]));
}
__device__ __forceinline__ float ex2f(float x) {
    float y;
    asm("ex2.approx.ftz.f32 %0, %1;" : "=f"(y) : "f"(x));
    return y;
}
// Split pair (a,b) into packed bf16x2 hi and lo (low half = a)
__device__ __forceinline__ void split2(float a, float b, uint32_t& hp, uint32_t& lp) {
    __nv_bfloat16 ha = __float2bfloat16(a), hb = __float2bfloat16(b);
    float la = a - __bfloat162float(ha);
    float lb = b - __bfloat162float(hb);
    __nv_bfloat162 hv(ha, hb);
    __nv_bfloat162 lv(__float2bfloat16(la), __float2bfloat16(lb));
    hp = *(uint32_t*)&hv;
    lp = *(uint32_t*)&lv;
}

// ===========================================================================
// Fused split: x + 4 weights -> bf16 hi/lo, one launch.
// ===========================================================================
#define XF4 (Nn*DM/4)        // 1048576 float4s
#define WF4 (DM*DM/4)        // 262144 float4s per weight

struct SArgs { const float *x, *w0, *w1, *w2, *w3; };

__global__ void split_all_kernel(SArgs s,
                                 __nv_bfloat16* __restrict__ Ahi,
                                 __nv_bfloat16* __restrict__ Alo,
                                 __nv_bfloat16* __restrict__ Whi,
                                 __nv_bfloat16* __restrict__ Wlo)
{
    const int i = blockIdx.x * blockDim.x + threadIdx.x;
    const float* src; __nv_bfloat16 *hi, *lo; int idx;
    if (i < XF4) {
        src = s.x; hi = Ahi; lo = Alo; idx = i;
    } else {
        const int j = i - XF4;
        const int w = j >> 18;            // WF4 = 2^18
        idx = j & (WF4 - 1);
        src = (w == 0) ? s.w0 : (w == 1) ? s.w1 : (w == 2) ? s.w2 : s.w3;
        hi = Whi + (size_t)w * (DM*DM);
        lo = Wlo + (size_t)w * (DM*DM);
    }
    float4 f = ((const float4*)src)[idx];
    __nv_bfloat16 h[4], l[4];
    float v[4] = {f.x, f.y, f.z, f.w};
#pragma unroll
    for (int j = 0; j < 4; j++) {
        h[j] = __float2bfloat16(v[j]);
        l[j] = __float2bfloat16(v[j] - __bfloat162float(h[j]));
    }
    ((uint2*)hi)[idx] = *(uint2*)h;
    ((uint2*)lo)[idx] = *(uint2*)l;
}

// ===========================================================================
// bf16-split GEMM (mma.sync): CTA tile 256x128, warp tile 64x64 (4m x 2n),
// K-chunk 32, 2-stage, 1 CTA/SM. High MMA/ldsm ratio -> LDS no longer binds.
// Stage (48KB): sA 0: 256 rows x 128B (u0-3 hi k0..31, u4-7 lo, swz u^(r&7))
//               sB 32768: hi 32 krows x 256B, lo +8192, swz (u&8)|((u&7)^(r&7))
// ===========================================================================
#define GSTAGE 49152
#define GEMM_SMEM (2*GSTAGE)   // 96KB

struct GArgs {
    const __nv_bfloat16 *Ahi, *Alo, *Wh, *Wl;   // Wh/Wl: base of 4 matrices
    const float *b0, *b1, *b2, *b3;
    float *outf;
    __nv_bfloat16 *q_h, *q_l, *k_h, *k_l, *v_h, *v_l;
    int mode_sel;
};

__global__ __launch_bounds__(256, 1)
void gemm_bf16split(GArgs a)
{
    extern __shared__ __align__(1024) char sm[];
    const uint32_t sb = smem_u32(sm);
    const int mode = (a.mode_sel < 0) ? (int)blockIdx.z : a.mode_sel;

    const __nv_bfloat16* Whi = a.Wh + (size_t)mode * DM * DM;
    const __nv_bfloat16* Wlo = a.Wl + (size_t)mode * DM * DM;
    const float* bias = (mode == 0) ? a.b0 : (mode == 1) ? a.b1
                       : (mode == 2) ? a.b2 : a.b3;
    __nv_bfloat16* outh = (mode == 0) ? a.q_h : (mode == 1) ? a.k_h : a.v_h;
    __nv_bfloat16* outl = (mode == 0) ? a.q_l : (mode == 1) ? a.k_l : a.v_l;

    const int tid  = threadIdx.x;
    const int wid  = tid >> 5;
    const int lane = tid & 31;
    const int wm   = wid >> 1;            // 0..3, 64 rows each
    const int wn   = wid & 1;             // 0..1, 64 cols each
    const int row0 = blockIdx.y * 256;
    const int col0 = blockIdx.x * 128;

    // ---- cp.async: A row per thread (8 units), B 4 units per thread ----
    const int a_r = tid;                   // 0..255
    const __nv_bfloat16* aHrow = a.Ahi + (size_t)(row0 + a_r) * DM;
    const __nv_bfloat16* aLrow = a.Alo + (size_t)(row0 + a_r) * DM;

    const int b_arr = tid >> 7;            // 0 hi, 1 lo
    const int b_r   = (tid & 127) >> 2;    // 0..31
    const int b_u0  = (tid & 3) * 4;       // 0,4,8,12
    const __nv_bfloat16* bSrc =
        (b_arr ? Wlo : Whi) + (size_t)b_r * DM + col0;

    uint32_t a_dst[8], b_dst[4];
#pragma unroll
    for (int u = 0; u < 8; u++)
        a_dst[u] = (uint32_t)(a_r * 128 + ((u ^ (a_r & 7))) * 16);
#pragma unroll
    for (int i = 0; i < 4; i++) {
        const int bu = b_u0 + i;
        b_dst[i] = (uint32_t)(32768 + b_arr * 8192 + b_r * 256
                              + (((bu & 8) | ((bu & 7) ^ (b_r & 7)))) * 16);
    }

    const int q8l = (lane >> 3) & 1;
    const int q8h = lane >> 4;
    const int rr  = lane & 7;

    float acc[4][8][4];
#pragma unroll
    for (int mi = 0; mi < 4; mi++)
#pragma unroll
        for (int nf = 0; nf < 8; nf++)
#pragma unroll
            for (int e = 0; e < 4; e++) acc[mi][nf][e] = 0.f;

    // ---- prologue: issue chunk 0 ----
#pragma unroll
    for (int u = 0; u < 8; u++)
        CP_ASYNC16(sb + a_dst[u], (u < 4 ? aHrow + u*8 : aLrow + (u-4)*8));
#pragma unroll
    for (int i = 0; i < 4; i++)
        CP_ASYNC16(sb + b_dst[i], bSrc + (b_u0 + i) * 8);
    CP_COMMIT();

    for (int c = 0; c < 32; c++) {
        CP_WAIT(0);
        __syncthreads();
        if (c + 1 < 32) {
            const uint32_t st2 = sb + ((c + 1) & 1) * GSTAGE;
            const int k0 = (c + 1) * 32;
#pragma unroll
            for (int u = 0; u < 8; u++)
                CP_ASYNC16(st2 + a_dst[u],
                           (u < 4 ? aHrow + k0 + u*8 : aLrow + k0 + (u-4)*8));
#pragma unroll
            for (int i = 0; i < 4; i++)
                CP_ASYNC16(st2 + b_dst[i], bSrc + (size_t)k0 * DM + (b_u0 + i) * 8);
            CP_COMMIT();
        }

        const uint32_t st = sb + (c & 1) * GSTAGE;
#pragma unroll
        for (int s = 0; s < 2; s++) {
            uint32_t ah[4][4], al[4][4];
#pragma unroll
            for (int mi = 0; mi < 4; mi++) {
                const int arow = wm * 64 + mi * 16 + q8l * 8 + rr;
                ldsm_x4(ah[mi], st + (uint32_t)(arow * 128
                                 + ((2*s + q8h) ^ (arow & 7)) * 16));
                ldsm_x4(al[mi], st + (uint32_t)(arow * 128
                                 + ((4 + 2*s + q8h) ^ (arow & 7)) * 16));
            }
#pragma unroll
            for (int ng = 0; ng < 4; ng++) {
                const int krow = 16 * s + q8l * 8 + rr;
                const int u = wn * 8 + ng * 2 + q8h;
                const uint32_t ob = (uint32_t)(32768 + krow * 256
                                  + (((u & 8) | ((u & 7) ^ (krow & 7)))) * 16);
                uint32_t bh4[4], bl4[4];
                ldsm_x4_t(bh4, st + ob);
                ldsm_x4_t(bl4, st + ob + 8192);
#pragma unroll
                for (int mi = 0; mi < 4; mi++) {
                    mma_bf16(acc[mi][ng*2],   ah[mi], bh4);
                    mma_bf16(acc[mi][ng*2+1], ah[mi], bh4 + 2);
                    mma_bf16(acc[mi][ng*2],   ah[mi], bl4);
                    mma_bf16(acc[mi][ng*2+1], ah[mi], bl4 + 2);
                    mma_bf16(acc[mi][ng*2],   al[mi], bh4);
                    mma_bf16(acc[mi][ng*2+1], al[mi], bh4 + 2);
                }
            }
        }
    }

    // --- epilogue ----------------------------------------------------------
    float bias_v[16];
#pragma unroll
    for (int nf = 0; nf < 8; nf++)
#pragma unroll
        for (int ec = 0; ec < 2; ec++)
            bias_v[nf*2 + ec] = __ldg(&bias[col0 + wn*64 + nf*8 + (lane&3)*2 + ec]);

    float invf[8];
    if (mode < 2) {
#pragma unroll
        for (int nf = 0; nf < 4; nf++)
#pragma unroll
            for (int ec = 0; ec < 2; ec++) {
                const int j = nf*8 + (lane&3)*2 + ec;
                invf[nf*2 + ec] = powf(10000.f, -(float)j / 32.f);
            }
    }
    const int h_idx = blockIdx.x * 2 + wn;
    const float oscale = (mode == 0) ? QSCALE : 1.f;

#pragma unroll
    for (int mi = 0; mi < 4; mi++) {
#pragma unroll
        for (int er = 0; er < 2; er++) {
            const int m = wm*64 + mi*16 + (lane >> 2) + er*8;
            const int n = row0 + m;
            const int b = n >> 11;
            const int s = n & 2047;
            if (mode < 2) {
                float y1[8], y2[8];
#pragma unroll
                for (int nf = 0; nf < 4; nf++)
#pragma unroll
                    for (int ec = 0; ec < 2; ec++) {
                        const int ii = nf*2 + ec;
                        float sn, cs;
                        sincosf((float)s * invf[ii], &sn, &cs);
                        const float x1 = acc[mi][nf][er*2 + ec]   + bias_v[ii];
                        const float x2 = acc[mi][nf+4][er*2 + ec] + bias_v[ii + 8];
                        y1[ii] = (x1 * cs - x2 * sn) * oscale;
                        y2[ii] = (x2 * cs + x1 * sn) * oscale;
                    }
                __nv_bfloat16* dh = outh + (((size_t)(b*Hh + h_idx))*Ss + s)*Dd;
                __nv_bfloat16* dl = outl + (((size_t)(b*Hh + h_idx))*Ss + s)*Dd;
#pragma unroll
                for (int nf = 0; nf < 4; nf++) {
                    const int d = nf*8 + (lane&3)*2;
                    uint32_t hp, lp;
                    split2(y1[nf*2], y1[nf*2+1], hp, lp);
                    *(uint32_t*)(dh + d) = hp; *(uint32_t*)(dl + d) = lp;
                    split2(y2[nf*2], y2[nf*2+1], hp, lp);
                    *(uint32_t*)(dh + d + 32) = hp; *(uint32_t*)(dl + d + 32) = lp;
                }
            } else if (mode == 2) {
                __nv_bfloat16* dh = outh + (((size_t)(b*Hh + h_idx))*Ss + s)*Dd;
                __nv_bfloat16* dl = outl + (((size_t)(b*Hh + h_idx))*Ss + s)*Dd;
#pragma unroll
                for (int nf = 0; nf < 8; nf++) {
                    const int d = nf*8 + (lane&3)*2;
                    uint32_t hp, lp;
                    split2(acc[mi][nf][er*2] + bias_v[nf*2],
                           acc[mi][nf][er*2+1] + bias_v[nf*2+1], hp, lp);
                    *(uint32_t*)(dh + d) = hp; *(uint32_t*)(dl + d) = lp;
                }
            } else {
                float* dst = a.outf + (size_t)n * DM + col0 + wn*64;
#pragma unroll
                for (int nf = 0; nf < 8; nf++)
#pragma unroll
                    for (int ec = 0; ec < 2; ec++)
                        dst[nf*8 + (lane&3)*2 + ec] =
                            acc[mi][nf][er*2 + ec] + bias_v[nf*2 + ec];
            }
        }
    }
}

// ===========================================================================
// Flash attention on mma.sync. CTA: 256 q-rows (warp owns 32 rows), KV tile
// 64 double-buffered. 1 CTA/SM. Q frags reloaded from smem per tile.
// smem: Qhi 32K | Qlo 32K | 2 KV stages of 32K (Khi 8K|Klo 8K|Vhi 8K|Vlo 8K)
// ===========================================================================
#define AKV_OFF   65536
#define AKV_SZ    32768
#define ATTN_SMEM (AKV_OFF + 2*AKV_SZ)    // 131072

__global__ __launch_bounds__(256, 1)
void attn_mma_kernel()
{
    extern __shared__ __align__(1024) char sm[];
    const uint32_t sb = smem_u32(sm);
    const int tid  = threadIdx.x;
    const int wid  = tid >> 5;
    const int lane = tid & 31;
    const int qt   = blockIdx.x;     // 0..7 (256 rows each)
    const int bh   = blockIdx.y;
    const int b    = bh >> 4;
    const int h    = bh & 15;

    const int q8l = (lane >> 3) & 1;
    const int q8h = lane >> 4;
    const int rr  = lane & 7;

    // cp.async: Q — one row per thread (hi + lo)
    const __nv_bfloat16* gqh = g_Qhi + ((size_t)bh*Ss + qt*256 + tid)*Dd;
    const __nv_bfloat16* gql = g_Qlo + ((size_t)bh*Ss + qt*256 + tid)*Dd;
    // KV: hi/lo halves of the block
    const int ca  = tid >> 7;          // 0 = hi, 1 = lo
    const int kr  = (tid & 127) >> 1;  // KV row 0..63
    const int kh0 = (tid & 1) * 4;     // unit base
    const __nv_bfloat16* gk = (ca ? g_Klo : g_Khi) + ((size_t)bh*Ss + kr)*Dd;
    const __nv_bfloat16* gv = (ca ? g_Vlo : g_Vhi) + ((size_t)bh*Ss + kr)*Dd;

    uint32_t kdst[4], vdst[4];
#pragma unroll
    for (int i = 0; i < 4; i++) {
        const int u = kh0 + i;
        const uint32_t sw = (uint32_t)((u ^ (kr & 7)) * 16);
        kdst[i] = (uint32_t)(ca*8192 + kr*128) + sw;
        vdst[i] = (uint32_t)(16384 + ca*8192 + kr*128) + sw;
    }

    // ldmatrix lane bases
    const uint32_t krow_b = (uint32_t)((q8h*8 + rr) * 128);           // K b-frag rows
    const uint32_t vrow_b = (uint32_t)((q8l*8 + rr) * 128);           // V b-frag rows

    // prologue: load Q (hi+lo) + tile 0
#pragma unroll
    for (int u = 0; u < 8; u++) {
        const uint32_t sw = (uint32_t)((u ^ (tid & 7)) * 16);
        CP_ASYNC16(sb + (uint32_t)(tid*128) + sw,         gqh + u*8);
        CP_ASYNC16(sb + 32768 + (uint32_t)(tid*128) + sw, gql + u*8);
    }
#pragma unroll
    for (int i = 0; i < 4; i++) {
        CP_ASYNC16(sb + AKV_OFF + kdst[i], gk + (kh0 + i)*8);
        CP_ASYNC16(sb + AKV_OFF + vdst[i], gv + (kh0 + i)*8);
    }
    CP_COMMIT();

    float o_acc[2][8][4];
    float m_i[2][2], l_i[2][2];
#pragma unroll
    for (int mi = 0; mi < 2; mi++) {
#pragma unroll
        for (int er = 0; er < 2; er++) { m_i[mi][er] = -1e30f; l_i[mi][er] = 0.f; }
#pragma unroll
        for (int nf = 0; nf < 8; nf++)
#pragma unroll
            for (int e = 0; e < 4; e++) o_acc[mi][nf][e] = 0.f;
    }

    for (int nt = 0; nt < 32; nt++) {
        CP_WAIT(0);
        __syncthreads();

        if (nt + 1 < 32) {
            const uint32_t kb = sb + AKV_OFF + ((nt + 1) & 1) * AKV_SZ;
            const size_t s0 = (size_t)(nt + 1) * 64 * Dd;
#pragma unroll
            for (int i = 0; i < 4; i++) {
                CP_ASYNC16(kb + kdst[i], gk + s0 + (kh0 + i)*8);
                CP_ASYNC16(kb + vdst[i], gv + s0 + (kh0 + i)*8);
            }
            CP_COMMIT();
        }

        const uint32_t kbase = sb + AKV_OFF + (nt & 1) * AKV_SZ;

        // ---- S = Q K^T  (32 rows x 64 cols per warp) ----
        float sacc[2][8][4];
#pragma unroll
        for (int mi = 0; mi < 2; mi++)
#pragma unroll
            for (int nf = 0; nf < 8; nf++)
#pragma unroll
                for (int e = 0; e < 4; e++) sacc[mi][nf][e] = 0.f;

#pragma unroll
        for (int kc = 0; kc < 4; kc++) {
            uint32_t qh_f[2][4], ql_f[2][4];
#pragma unroll
            for (int mi = 0; mi < 2; mi++) {
                const int qrow = wid*32 + mi*16 + q8l*8 + rr;
                const uint32_t qa = sb + (uint32_t)(qrow * 128
                                  + ((kc*2 + q8h) ^ (qrow & 7)) * 16);
                ldsm_x4(qh_f[mi], qa);
                ldsm_x4(ql_f[mi], qa + 32768);
            }
#pragma unroll
            for (int ng = 0; ng < 4; ng++) {
                const uint32_t ko = kbase + (uint32_t)(ng * 2048) + krow_b
                                  + (uint32_t)(((kc*2 + q8l) ^ rr) * 16);
                uint32_t kh4[4], kl4[4];
                ldsm_x4(kh4, ko);
                ldsm_x4(kl4, ko + 8192);
#pragma unroll
                for (int mi = 0; mi < 2; mi++) {
                    mma_bf16(sacc[mi][ng*2],   qh_f[mi], kh4);
                    mma_bf16(sacc[mi][ng*2+1], qh_f[mi], kh4 + 2);
                    mma_bf16(sacc[mi][ng*2],   qh_f[mi], kl4);
                    mma_bf16(sacc[mi][ng*2+1], qh_f[mi], kl4 + 2);
                    mma_bf16(sacc[mi][ng*2],   ql_f[mi], kh4);
                    mma_bf16(sacc[mi][ng*2+1], ql_f[mi], kh4 + 2);
                }
            }
        }

        // ---- online softmax (in-register, quad shfl) ----
#pragma unroll
        for (int mi = 0; mi < 2; mi++) {
            float m_new[2], sc[2];
#pragma unroll
            for (int er = 0; er < 2; er++) {
                float mx = -1e30f;
#pragma unroll
                for (int nf = 0; nf < 8; nf++) {
                    mx = fmaxf(mx, sacc[mi][nf][er*2]);
                    mx = fmaxf(mx, sacc[mi][nf][er*2+1]);
                }
                mx = fmaxf(mx, __shfl_xor_sync(0xffffffffu, mx, 1));
                mx = fmaxf(mx, __shfl_xor_sync(0xffffffffu, mx, 2));
                m_new[er] = fmaxf(m_i[mi][er], mx);
                sc[er] = ex2f(m_i[mi][er] - m_new[er]);
            }
#pragma unroll
            for (int er = 0; er < 2; er++) {
                float rs = 0.f;
#pragma unroll
                for (int nf = 0; nf < 8; nf++) {
#pragma unroll
                    for (int ec = 0; ec < 2; ec++) {
                        float p = ex2f(sacc[mi][nf][er*2+ec] - m_new[er]);
                        sacc[mi][nf][er*2+ec] = p;
                        rs += p;
                    }
                }
                rs += __shfl_xor_sync(0xffffffffu, rs, 1);
                rs += __shfl_xor_sync(0xffffffffu, rs, 2);
                l_i[mi][er] = l_i[mi][er] * sc[er] + rs;
                m_i[mi][er] = m_new[er];
#pragma unroll
                for (int nf = 0; nf < 8; nf++) {
                    o_acc[mi][nf][er*2]   *= sc[er];
                    o_acc[mi][nf][er*2+1] *= sc[er];
                }
            }
        }

        // ---- O += P V ----
#pragma unroll
        for (int kc = 0; kc < 4; kc++) {
            uint32_t ph[2][4], pl[2][4];
#pragma unroll
            for (int mi = 0; mi < 2; mi++) {
                const float* cE = sacc[mi][2*kc];
                const float* cO = sacc[mi][2*kc+1];
                split2(cE[0], cE[1], ph[mi][0], pl[mi][0]);
                split2(cE[2], cE[3], ph[mi][1], pl[mi][1]);
                split2(cO[0], cO[1], ph[mi][2], pl[mi][2]);
                split2(cO[2], cO[3], ph[mi][3], pl[mi][3]);
            }
#pragma unroll
            for (int ng = 0; ng < 4; ng++) {
                const uint32_t vo = kbase + 16384 + (uint32_t)(kc * 2048) + vrow_b
                                  + (uint32_t)(((ng*2 + q8h) ^ rr) * 16);
                uint32_t vh[4], vl[4];
                ldsm_x4_t(vh, vo);
                ldsm_x4_t(vl, vo + 8192);
#pragma unroll
                for (int mi = 0; mi < 2; mi++) {
                    mma_bf16(o_acc[mi][ng*2],   ph[mi], vh);
                    mma_bf16(o_acc[mi][ng*2+1], ph[mi], vh + 2);
                    mma_bf16(o_acc[mi][ng*2],   pl[mi], vh);
                    mma_bf16(o_acc[mi][ng*2+1], pl[mi], vh + 2);
                    mma_bf16(o_acc[mi][ng*2],   ph[mi], vl);
                    mma_bf16(o_acc[mi][ng*2+1], ph[mi], vl + 2);
                }
            }
        }
    }

    // ---- epilogue: per-warp direct write ----
#pragma unroll
    for (int mi = 0; mi < 2; mi++) {
#pragma unroll
        for (int er = 0; er < 2; er++) {
            const int r = wid*32 + mi*16 + (lane >> 2) + er*8;
            const float inv = 1.f / l_i[mi][er];
            const size_t nrow = (size_t)(b*Ss + qt*256 + r) * DM + h*64;
#pragma unroll
            for (int nf = 0; nf < 8; nf++) {
                const int col = nf*8 + (lane & 3)*2;
                const float v0 = o_acc[mi][nf][er*2]   * inv;
                const float v1 = o_acc[mi][nf][er*2+1] * inv;
                uint32_t hp, lp;
                split2(v0, v1, hp, lp);
                *(uint32_t*)(g_Ahi + nrow + col) = hp;
                *(uint32_t*)(g_Alo + nrow + col) = lp;
            }
        }
    }
}

// ---------------------------------------------------------------------------
extern "C" void kernel_launch(void* const* d_in, const int* in_sizes, int n_in,
                              void* d_out, int out_size)
{
    const float* x  = (const float*)d_in[0];
    const float* wq = (const float*)d_in[1];
    const float* bq = (const float*)d_in[2];
    const float* wk = (const float*)d_in[3];
    const float* bk = (const float*)d_in[4];
    const float* wv = (const float*)d_in[5];
    const float* bv = (const float*)d_in[6];
    const float* wo = (const float*)d_in[7];
    const float* bo = (const float*)d_in[8];
    float* out = (float*)d_out;

    cudaFuncSetAttribute(gemm_bf16split,
                         cudaFuncAttributeMaxDynamicSharedMemorySize, GEMM_SMEM);
    cudaFuncSetAttribute(attn_mma_kernel,
                         cudaFuncAttributeMaxDynamicSharedMemorySize, ATTN_SMEM);

    __nv_bfloat16 *gAhi, *gAlo, *gWhi, *gWlo;
    __nv_bfloat16 *gQh, *gQl, *gKh, *gKl, *gVh, *gVl;
    cudaGetSymbolAddress((void**)&gAhi, g_Ahi);
    cudaGetSymbolAddress((void**)&gAlo, g_Alo);
    cudaGetSymbolAddress((void**)&gWhi, g_Whi);
    cudaGetSymbolAddress((void**)&gWlo, g_Wlo);
    cudaGetSymbolAddress((void**)&gQh, g_Qhi);
    cudaGetSymbolAddress((void**)&gQl, g_Qlo);
    cudaGetSymbolAddress((void**)&gKh, g_Khi);
    cudaGetSymbolAddress((void**)&gKl, g_Klo);
    cudaGetSymbolAddress((void**)&gVh, g_Vhi);
    cudaGetSymbolAddress((void**)&gVl, g_Vlo);

    // 0) Split x + all 4 weights in ONE launch
    SArgs sa; sa.x = x; sa.w0 = wq; sa.w1 = wk; sa.w2 = wv; sa.w3 = wo;
    split_all_kernel<<<(XF4 + 4*WF4) / 256, 256>>>(sa, gAhi, gAlo, gWhi, gWlo);

    GArgs ga;
    ga.Ahi = gAhi; ga.Alo = gAlo; ga.Wh = gWhi; ga.Wl = gWlo;
    ga.b0 = bq; ga.b1 = bk; ga.b2 = bv; ga.b3 = bo;
    ga.outf = out;
    ga.q_h = gQh; ga.q_l = gQl; ga.k_h = gKh; ga.k_l = gKl;
    ga.v_h = gVh; ga.v_l = gVl;

    // 1) Fused Q/K/V projections (one launch, blockIdx.z selects)
    ga.mode_sel = -1;
    gemm_bf16split<<<dim3(DM/128, Nn/256, 3), 256, GEMM_SMEM>>>(ga);
    // 2) Flash attention on tensor cores (writes g_Ahi/g_Alo)
    attn_mma_kernel<<<dim3(Ss / 256, BH), 256, ATTN_SMEM>>>();
    // 3) Output projection (fp32 out)
    ga.mode_sel = 3;
    gemm_bf16split<<<dim3(DM/128, Nn/256, 1), 256, GEMM_SMEM>>>(ga);
}